// round 4
// baseline (speedup 1.0000x reference)
#include <cuda_runtime.h>
#include <math.h>

#define NN 65536
#define EPSV 1e-5f

// ---------------- scratch (static __device__, allocation-free) ----------------
static __device__ float g_h  [4*64*NN];     // LN1 output
static __device__ float g_hc [4*64*NN];     // depthwise conv output
static __device__ float g_y  [4*64*NN];     // first residual output
static __device__ float g_t  [4*256*NN];    // mlp_in output (256 ch)
static __device__ float g_covp[4*64*4096];  // covariance partials
static __device__ float g_C  [4*4096];      // covariance
static __device__ float g_W3 [4*4096];      // fused attn matrix per batch

// ---------------- K1: LayerNorm over channels (per pixel) ----------------
__global__ void __launch_bounds__(256) k_ln1(const float* __restrict__ x,
                                             const float* __restrict__ w,
                                             const float* __restrict__ bias){
    int i = blockIdx.x*256 + threadIdx.x;
    int b = i >> 16, n = i & (NN-1);
    const float* xp = x + (b*64)*NN + n;
    float xv[64]; float s = 0.f;
#pragma unroll
    for(int c=0;c<64;c++){ xv[c]=xp[c*NN]; s+=xv[c]; }
    float mu = s*(1.f/64.f), vs = 0.f;
#pragma unroll
    for(int c=0;c<64;c++){ float d=xv[c]-mu; vs+=d*d; }
    float rstd = rsqrtf(vs*(1.f/64.f) + EPSV);
    float* hp = g_h + (b*64)*NN + n;
#pragma unroll
    for(int c=0;c<64;c++) hp[c*NN] = (xv[c]-mu)*rstd*__ldg(&w[c]) + __ldg(&bias[c]);
}

// ---------------- K2: depthwise 3x3, zero pad ----------------
__global__ void __launch_bounds__(256) k_dw1(const float* __restrict__ dww){
    __shared__ float sh[10][34];
    int z = blockIdx.z, b = z>>6, c = z&63;
    int tx0 = blockIdx.x*32, ty0 = blockIdx.y*8;
    int tid = threadIdx.y*32 + threadIdx.x;
    const float* hp = g_h + (b*64+c)*NN;
    for(int i=tid;i<340;i+=256){
        int r = i/34, cc = i - r*34;
        int gy = ty0 + r - 1, gx = tx0 + cc - 1;
        sh[r][cc] = (gy>=0 && gy<256 && gx>=0 && gx<256) ? hp[gy*256 + gx] : 0.f;
    }
    float wv[9];
#pragma unroll
    for(int k=0;k<9;k++) wv[k] = __ldg(&dww[c*9+k]);
    __syncthreads();
    float acc = 0.f;
#pragma unroll
    for(int ky=0;ky<3;ky++)
#pragma unroll
        for(int kx=0;kx<3;kx++)
            acc += sh[threadIdx.y+ky][threadIdx.x+kx]*wv[ky*3+kx];
    g_hc[(b*64+c)*NN + (ty0+threadIdx.y)*256 + tx0+threadIdx.x] = acc;
}

// ---------------- K3: channel covariance C = sum_n hc hc^T (partials) ----------------
__global__ void __launch_bounds__(256) k_cov(){
    __shared__ float s_h[64][65];
    int b = blockIdx.y, blk = blockIdx.x;
    int tid = threadIdx.x;
    int ti = tid>>4, tj = tid&15;
    float acc[4][4];
#pragma unroll
    for(int r=0;r<4;r++)
#pragma unroll
        for(int cc=0;cc<4;cc++) acc[r][cc]=0.f;
    const float* hp = g_hc + b*64*NN;
    for(int tile=0;tile<16;tile++){
        int n0 = (blk*16 + tile)*64;
        for(int i=tid;i<4096;i+=256){
            int p = i&63, c = i>>6;
            s_h[p][c] = hp[c*NN + n0 + p];
        }
        __syncthreads();
#pragma unroll 4
        for(int p=0;p<64;p++){
            float a0=s_h[p][ti*4+0],a1=s_h[p][ti*4+1],a2=s_h[p][ti*4+2],a3=s_h[p][ti*4+3];
            float b0=s_h[p][tj*4+0],b1=s_h[p][tj*4+1],b2=s_h[p][tj*4+2],b3=s_h[p][tj*4+3];
            acc[0][0]+=a0*b0; acc[0][1]+=a0*b1; acc[0][2]+=a0*b2; acc[0][3]+=a0*b3;
            acc[1][0]+=a1*b0; acc[1][1]+=a1*b1; acc[1][2]+=a1*b2; acc[1][3]+=a1*b3;
            acc[2][0]+=a2*b0; acc[2][1]+=a2*b1; acc[2][2]+=a2*b2; acc[2][3]+=a2*b3;
            acc[3][0]+=a3*b0; acc[3][1]+=a3*b1; acc[3][2]+=a3*b2; acc[3][3]+=a3*b3;
        }
        __syncthreads();
    }
    float* op = g_covp + (b*64+blk)*4096;
#pragma unroll
    for(int r=0;r<4;r++)
#pragma unroll
        for(int cc=0;cc<4;cc++)
            op[(ti*4+r)*64 + tj*4+cc] = acc[r][cc];
}

// ---------------- K4: reduce covariance partials ----------------
__global__ void __launch_bounds__(256) k_covred(){
    int b = blockIdx.y;
    int e = blockIdx.x*256 + threadIdx.x;
    const float* p = g_covp + b*64*4096 + e;
    float s = 0.f;
    for(int k=0;k<64;k++) s += p[k*4096];
    g_C[b*4096 + e] = s;
}

// ---------------- K5: per-batch attention algebra -> W3 ----------------
__global__ void __launch_bounds__(256) k_attn(const float* __restrict__ qw,
                                              const float* __restrict__ kw,
                                              const float* __restrict__ vw,
                                              const float* __restrict__ pw){
    __shared__ float s_C[4096];
    __shared__ float s_M[4096];
    __shared__ float s_G[512];
    __shared__ float s_rq[64], s_rk[64], s_rv[64];
    int b = blockIdx.x, tid = threadIdx.x;
    for(int i=tid;i<4096;i+=256) s_C[i] = g_C[b*4096+i];
    __syncthreads();
    // KC = kw * C
    for(int i=tid;i<4096;i+=256){
        int r=i>>6, c=i&63; float s=0.f;
        for(int j=0;j<64;j++) s += __ldg(&kw[r*64+j])*s_C[j*64+c];
        s_M[i]=s;
    }
    __syncthreads();
    if(tid<64){
        float s=0.f;
        for(int i2=0;i2<64;i2++) s += s_M[tid*64+i2]*__ldg(&kw[tid*64+i2]);
        s_rk[tid] = fmaxf(sqrtf(fmaxf(s,0.f)), 1e-12f);
    }
    // Gram G[h][d][e] = qw_{h8+d} . KC_{h8+e}
    for(int g=tid; g<512; g+=256){
        int h=g>>6, de=g&63, d=de>>3, e=de&7;
        int a=h*8+d, bc=h*8+e;
        float s=0.f;
        for(int i2=0;i2<64;i2++) s += __ldg(&qw[a*64+i2])*s_M[bc*64+i2];
        s_G[g]=s;
    }
    __syncthreads();
    // QC
    for(int i=tid;i<4096;i+=256){
        int r=i>>6, c=i&63; float s=0.f;
        for(int j=0;j<64;j++) s += __ldg(&qw[r*64+j])*s_C[j*64+c];
        s_M[i]=s;
    }
    __syncthreads();
    if(tid<64){
        float s=0.f;
        for(int i2=0;i2<64;i2++) s += s_M[tid*64+i2]*__ldg(&qw[tid*64+i2]);
        s_rq[tid] = fmaxf(sqrtf(fmaxf(s,0.f)), 1e-12f);
    }
    __syncthreads();
    // VC
    for(int i=tid;i<4096;i+=256){
        int r=i>>6, c=i&63; float s=0.f;
        for(int j=0;j<64;j++) s += __ldg(&vw[r*64+j])*s_C[j*64+c];
        s_M[i]=s;
    }
    __syncthreads();
    if(tid<64){
        float s=0.f;
        for(int i2=0;i2<64;i2++) s += s_M[tid*64+i2]*__ldg(&vw[tid*64+i2]);
        s_rv[tid] = fmaxf(sqrtf(fmaxf(s,0.f)), 1e-12f);
    }
    __syncthreads();
    // block-diag Ab = softmax(G*scale/(rq*rk)) / rv  into s_M
    for(int i=tid;i<4096;i+=256) s_M[i]=0.f;
    __syncthreads();
    if(tid<64){
        int h=tid>>3, d=tid&7;
        const float scale = 0.35355339059327373f; // 8^-0.5
        float l[8], mx=-1e30f;
        for(int e=0;e<8;e++){
            l[e] = s_G[h*64+d*8+e]*scale/(s_rq[h*8+d]*s_rk[h*8+e]);
            mx = fmaxf(mx, l[e]);
        }
        float sum=0.f;
        for(int e=0;e<8;e++){ l[e]=expf(l[e]-mx); sum+=l[e]; }
        float inv=1.f/sum;
        for(int e=0;e<8;e++)
            s_M[(h*8+d)*64 + h*8+e] = l[e]*inv / s_rv[h*8+e];
    }
    __syncthreads();
    // W2 = proj * Ab (exploit block-diag: 8 terms)  -> reuse s_C
    for(int i=tid;i<4096;i+=256){
        int r=i>>6, c=i&63, h=c>>3;
        float s=0.f;
        for(int d=0;d<8;d++){ int m=h*8+d; s += __ldg(&pw[r*64+m])*s_M[m*64+c]; }
        s_C[i]=s;
    }
    __syncthreads();
    // W3 = W2 * vw
    for(int i=tid;i<4096;i+=256){
        int r=i>>6, c=i&63;
        float s=0.f;
        for(int m=0;m<64;m++) s += s_C[r*64+m]*__ldg(&vw[m*64+c]);
        g_W3[b*4096+i]=s;
    }
}

// ---------------- K6: y = x + W3*hc ; LN2 ; t = mlp_in*m ----------------
__global__ void __launch_bounds__(256) k_resid1(const float* __restrict__ x,
                                                const float* __restrict__ lw,
                                                const float* __restrict__ lb,
                                                const float* __restrict__ mw){
    __shared__ float s_w3[4096];
    __shared__ float s_mw[8192];
    int tid = threadIdx.x;
    int i = blockIdx.x*256 + tid;
    int b = i>>16, n = i&(NN-1);
    for(int j=tid;j<4096;j+=256) s_w3[j] = g_W3[b*4096+j];
    float hc[64], a[64];
    const float* hp = g_hc + b*64*NN + n;
    const float* xp = x    + b*64*NN + n;
#pragma unroll
    for(int c=0;c<64;c++) hc[c] = hp[c*NN];
    __syncthreads();
    float* yp = g_y + b*64*NN + n;
#pragma unroll
    for(int c=0;c<64;c++){
        const float4* w4 = (const float4*)(s_w3 + c*64);
        float s0=0.f,s1=0.f,s2=0.f,s3=0.f;
#pragma unroll
        for(int j=0;j<16;j++){
            float4 w = w4[j];
            s0 += w.x*hc[4*j+0]; s1 += w.y*hc[4*j+1];
            s2 += w.z*hc[4*j+2]; s3 += w.w*hc[4*j+3];
        }
        float yv = xp[c*NN] + ((s0+s1)+(s2+s3));
        a[c] = yv;
        yp[c*NN] = yv;
    }
    // LN2
    float s = 0.f;
#pragma unroll
    for(int c=0;c<64;c++) s += a[c];
    float mu = s*(1.f/64.f), vs = 0.f;
#pragma unroll
    for(int c=0;c<64;c++){ float d=a[c]-mu; vs+=d*d; }
    float rstd = rsqrtf(vs*(1.f/64.f) + EPSV);
#pragma unroll
    for(int c=0;c<64;c++) a[c] = (a[c]-mu)*rstd*__ldg(&lw[c]) + __ldg(&lb[c]);
    // mlp_in: 256 outputs in 2 chunks of 128 (weights staged in smem)
    float* tp = g_t + b*256*NN + n;
    for(int ch=0;ch<2;ch++){
        for(int j=tid;j<8192;j+=256) s_mw[j] = mw[ch*8192+j];
        __syncthreads();
#pragma unroll 1
        for(int o=0;o<128;o++){
            const float4* w4 = (const float4*)(s_mw + o*64);
            float s0=0.f,s1=0.f,s2=0.f,s3=0.f;
#pragma unroll
            for(int j=0;j<16;j++){
                float4 w = w4[j];
                s0 += w.x*a[4*j+0]; s1 += w.y*a[4*j+1];
                s2 += w.z*a[4*j+2]; s3 += w.w*a[4*j+3];
            }
            tp[(ch*128+o)*NN] = (s0+s1)+(s2+s3);
        }
        __syncthreads();
    }
}

// ---------------- K7: reflect-pad grouped 3x3 + SiLU gate + BN + out_w + residual ----------------
__global__ void __launch_bounds__(256) k_mlp2(const float* __restrict__ dww,
                                              const float* __restrict__ bg,
                                              const float* __restrict__ bb,
                                              const float* __restrict__ bm,
                                              const float* __restrict__ bv,
                                              const float* __restrict__ ow,
                                              float* __restrict__ out){
    __shared__ float s_owT[4096];         // out_w transposed: [j][o]
    __shared__ float s_dw[4608];
    __shared__ float s_t[8][10][34];
    int b = blockIdx.z;
    int tx0 = blockIdx.x*32, ty0 = blockIdx.y*8;
    int tid = threadIdx.y*32 + threadIdx.x;
    int px = threadIdx.x, py = threadIdx.y;
    for(int i=tid;i<4096;i+=256){ int o=i&63, j=i>>6; s_owT[j*64+o] = ow[o*64+j]; }
    for(int i=tid;i<4608;i+=256) s_dw[i] = dww[i];
    float acc[64];
#pragma unroll
    for(int o=0;o<64;o++) acc[o]=0.f;
    for(int g=0; g<32; g++){
        __syncthreads();
        for(int i=tid;i<2720;i+=256){
            int ch = i/340, rem = i - ch*340, r = rem/34, cc = rem - r*34;
            int gch = (ch<4) ? (4*g + ch) : (4*(32+g) + ch - 4);
            int gy = ty0 + r - 1;  gy = gy<0 ? -gy : (gy>255 ? 510-gy : gy);
            int gx = tx0 + cc - 1; gx = gx<0 ? -gx : (gx>255 ? 510-gx : gx);
            s_t[ch][r][cc] = g_t[(b*256 + gch)*NN + gy*256 + gx];
        }
        __syncthreads();
        float c0=0.f, c1=0.f, c2=0.f, c3=0.f;
#pragma unroll
        for(int ci=0;ci<4;ci++)
#pragma unroll
            for(int ky=0;ky<3;ky++)
#pragma unroll
                for(int kx=0;kx<3;kx++){
                    float t1 = s_t[ci  ][py+ky][px+kx];
                    float t2 = s_t[ci+4][py+ky][px+kx];
                    int wi = ci*9 + ky*3 + kx;
                    c0 += t1*s_dw[(2*g  )*36 + wi];
                    c1 += t1*s_dw[(2*g+1)*36 + wi];
                    c2 += t2*s_dw[(64+2*g)*36 + wi];
                    c3 += t2*s_dw[(65+2*g)*36 + wi];
                }
#pragma unroll
        for(int q=0;q<2;q++){
            int j = 2*g + q;
            float v1 = q ? c1 : c0;
            float v2 = q ? c3 : c2;
            float gg = v1/(1.f + __expf(-v1)) * v2;       // silu(x1)*x2
            gg = (gg - __ldg(&bm[j]))*rsqrtf(__ldg(&bv[j])+EPSV)*__ldg(&bg[j]) + __ldg(&bb[j]);
            const float4* w4 = (const float4*)(s_owT + j*64);
#pragma unroll
            for(int o4=0;o4<16;o4++){
                float4 w = w4[o4];
                acc[4*o4+0]+=w.x*gg; acc[4*o4+1]+=w.y*gg;
                acc[4*o4+2]+=w.z*gg; acc[4*o4+3]+=w.w*gg;
            }
        }
    }
    int n = (ty0+py)*256 + tx0+px;
    const float* yp = g_y + b*64*NN + n;
    float* op = out + b*64*NN + n;
#pragma unroll
    for(int o=0;o<64;o++) op[o*NN] = yp[o*NN] + acc[o];
}

// ---------------- launcher ----------------
extern "C" void kernel_launch(void* const* d_in, const int* in_sizes, int n_in,
                              void* d_out, int out_size){
    const float* x        = (const float*)d_in[0];
    const float* ln1_w    = (const float*)d_in[1];
    const float* ln1_b    = (const float*)d_in[2];
    const float* ln2_w    = (const float*)d_in[3];
    const float* ln2_b    = (const float*)d_in[4];
    const float* dw_w     = (const float*)d_in[5];
    const float* q_w      = (const float*)d_in[6];
    const float* k_w      = (const float*)d_in[7];
    const float* v_w      = (const float*)d_in[8];
    const float* proj_w   = (const float*)d_in[9];
    const float* mlp_in_w = (const float*)d_in[10];
    const float* mlp_dw_w = (const float*)d_in[11];
    const float* bn_g     = (const float*)d_in[12];
    const float* bn_b     = (const float*)d_in[13];
    const float* bn_m     = (const float*)d_in[14];
    const float* bn_v     = (const float*)d_in[15];
    const float* out_w    = (const float*)d_in[16];
    float* out = (float*)d_out;

    k_ln1   <<<1024, 256>>>(x, ln1_w, ln1_b);
    k_dw1   <<<dim3(8,32,256), dim3(32,8)>>>(dw_w);
    k_cov   <<<dim3(64,4), 256>>>();
    k_covred<<<dim3(16,4), 256>>>();
    k_attn  <<<4, 256>>>(q_w, k_w, v_w, proj_w);
    k_resid1<<<1024, 256>>>(x, ln2_w, ln2_b, mlp_in_w);
    k_mlp2  <<<dim3(8,32,4), dim3(32,8)>>>(mlp_dw_w, bn_g, bn_b, bn_m, bn_v, out_w, out);
}

// round 5
// speedup vs baseline: 1.0470x; 1.0470x over previous
#include <cuda_runtime.h>
#include <math.h>

#define NN 65536
#define EPSV 1e-5f

typedef unsigned long long ull;

// ---------------- packed f32x2 helpers (Blackwell FFMA2) ----------------
__device__ __forceinline__ ull pk(float lo, float hi){
    ull r; asm("mov.b64 %0,{%1,%2};" : "=l"(r) : "f"(lo), "f"(hi)); return r;
}
__device__ __forceinline__ void upk(ull v, float& lo, float& hi){
    asm("mov.b64 {%0,%1},%2;" : "=f"(lo), "=f"(hi) : "l"(v));
}
__device__ __forceinline__ ull ffma2(ull a, ull b, ull c){
    ull d; asm("fma.rn.f32x2 %0,%1,%2,%3;" : "=l"(d) : "l"(a), "l"(b), "l"(c)); return d;
}

// ---------------- scratch ----------------
static __device__ float g_h  [4*64*NN];
static __device__ float g_hc [4*64*NN];
static __device__ float g_y  [4*64*NN];
static __device__ float g_t  [4*256*NN];
static __device__ float g_covp[4*64*4096];
static __device__ float g_C  [4*4096];
static __device__ float g_W3 [4*4096];

// ---------------- K1: LayerNorm over channels ----------------
__global__ void __launch_bounds__(256) k_ln1(const float* __restrict__ x,
                                             const float* __restrict__ w,
                                             const float* __restrict__ bias){
    int i = blockIdx.x*256 + threadIdx.x;
    int b = i >> 16, n = i & (NN-1);
    const float* xp = x + (b*64)*NN + n;
    float xv[64]; float s = 0.f;
#pragma unroll
    for(int c=0;c<64;c++){ xv[c]=xp[c*NN]; s+=xv[c]; }
    float mu = s*(1.f/64.f), vs = 0.f;
#pragma unroll
    for(int c=0;c<64;c++){ float d=xv[c]-mu; vs+=d*d; }
    float rstd = rsqrtf(vs*(1.f/64.f) + EPSV);
    float* hp = g_h + (b*64)*NN + n;
#pragma unroll
    for(int c=0;c<64;c++) hp[c*NN] = (xv[c]-mu)*rstd*__ldg(&w[c]) + __ldg(&bias[c]);
}

// ---------------- K2: depthwise 3x3, zero pad ----------------
__global__ void __launch_bounds__(256) k_dw1(const float* __restrict__ dww){
    __shared__ float sh[10][34];
    int z = blockIdx.z, b = z>>6, c = z&63;
    int tx0 = blockIdx.x*32, ty0 = blockIdx.y*8;
    int tid = threadIdx.y*32 + threadIdx.x;
    const float* hp = g_h + (b*64+c)*NN;
    for(int i=tid;i<340;i+=256){
        int r = i/34, cc = i - r*34;
        int gy = ty0 + r - 1, gx = tx0 + cc - 1;
        sh[r][cc] = (gy>=0 && gy<256 && gx>=0 && gx<256) ? hp[gy*256 + gx] : 0.f;
    }
    float wv[9];
#pragma unroll
    for(int k=0;k<9;k++) wv[k] = __ldg(&dww[c*9+k]);
    __syncthreads();
    float acc = 0.f;
#pragma unroll
    for(int ky=0;ky<3;ky++)
#pragma unroll
        for(int kx=0;kx<3;kx++)
            acc += sh[threadIdx.y+ky][threadIdx.x+kx]*wv[ky*3+kx];
    g_hc[(b*64+c)*NN + (ty0+threadIdx.y)*256 + tx0+threadIdx.x] = acc;
}

// ---------------- K3: channel covariance partials (packed FMA) ----------------
__global__ void __launch_bounds__(256) k_cov(){
    __shared__ float s_h[64][65];
    int b = blockIdx.y, blk = blockIdx.x;
    int tid = threadIdx.x;
    int ti = tid>>4, tj = tid&15;
    ull acc01[4], acc23[4];
#pragma unroll
    for(int r=0;r<4;r++){ acc01[r]=0ULL; acc23[r]=0ULL; }
    const float* hp = g_hc + b*64*NN;
    for(int tile=0;tile<16;tile++){
        int n0 = (blk*16 + tile)*64;
        for(int i=tid;i<4096;i+=256){
            int p = i&63, c = i>>6;
            s_h[p][c] = hp[c*NN + n0 + p];
        }
        __syncthreads();
#pragma unroll 4
        for(int p=0;p<64;p++){
            float a0=s_h[p][ti*4+0],a1=s_h[p][ti*4+1],a2=s_h[p][ti*4+2],a3=s_h[p][ti*4+3];
            float b0=s_h[p][tj*4+0],b1=s_h[p][tj*4+1],b2=s_h[p][tj*4+2],b3=s_h[p][tj*4+3];
            ull pb01=pk(b0,b1), pb23=pk(b2,b3);
            acc01[0]=ffma2(pk(a0,a0),pb01,acc01[0]); acc23[0]=ffma2(pk(a0,a0),pb23,acc23[0]);
            acc01[1]=ffma2(pk(a1,a1),pb01,acc01[1]); acc23[1]=ffma2(pk(a1,a1),pb23,acc23[1]);
            acc01[2]=ffma2(pk(a2,a2),pb01,acc01[2]); acc23[2]=ffma2(pk(a2,a2),pb23,acc23[2]);
            acc01[3]=ffma2(pk(a3,a3),pb01,acc01[3]); acc23[3]=ffma2(pk(a3,a3),pb23,acc23[3]);
        }
        __syncthreads();
    }
    float* op = g_covp + (b*64+blk)*4096;
#pragma unroll
    for(int r=0;r<4;r++){
        float u,v;
        upk(acc01[r],u,v);
        op[(ti*4+r)*64 + tj*4+0]=u; op[(ti*4+r)*64 + tj*4+1]=v;
        upk(acc23[r],u,v);
        op[(ti*4+r)*64 + tj*4+2]=u; op[(ti*4+r)*64 + tj*4+3]=v;
    }
}

// ---------------- K4: reduce covariance partials ----------------
__global__ void __launch_bounds__(256) k_covred(){
    int b = blockIdx.y;
    int e = blockIdx.x*256 + threadIdx.x;
    const float* p = g_covp + b*64*4096 + e;
    float s = 0.f;
    for(int k=0;k<64;k++) s += p[k*4096];
    g_C[b*4096 + e] = s;
}

// ---------------- K5: per-batch attention algebra -> W3 ----------------
__global__ void __launch_bounds__(256) k_attn(const float* __restrict__ qw,
                                              const float* __restrict__ kw,
                                              const float* __restrict__ vw,
                                              const float* __restrict__ pw){
    __shared__ float s_C[4096];
    __shared__ float s_M[4096];
    __shared__ float s_G[512];
    __shared__ float s_rq[64], s_rk[64], s_rv[64];
    int b = blockIdx.x, tid = threadIdx.x;
    for(int i=tid;i<4096;i+=256) s_C[i] = g_C[b*4096+i];
    __syncthreads();
    for(int i=tid;i<4096;i+=256){
        int r=i>>6, c=i&63; float s=0.f;
        for(int j=0;j<64;j++) s += __ldg(&kw[r*64+j])*s_C[j*64+c];
        s_M[i]=s;
    }
    __syncthreads();
    if(tid<64){
        float s=0.f;
        for(int i2=0;i2<64;i2++) s += s_M[tid*64+i2]*__ldg(&kw[tid*64+i2]);
        s_rk[tid] = fmaxf(sqrtf(fmaxf(s,0.f)), 1e-12f);
    }
    for(int g=tid; g<512; g+=256){
        int h=g>>6, de=g&63, d=de>>3, e=de&7;
        int a=h*8+d, bc=h*8+e;
        float s=0.f;
        for(int i2=0;i2<64;i2++) s += __ldg(&qw[a*64+i2])*s_M[bc*64+i2];
        s_G[g]=s;
    }
    __syncthreads();
    for(int i=tid;i<4096;i+=256){
        int r=i>>6, c=i&63; float s=0.f;
        for(int j=0;j<64;j++) s += __ldg(&qw[r*64+j])*s_C[j*64+c];
        s_M[i]=s;
    }
    __syncthreads();
    if(tid<64){
        float s=0.f;
        for(int i2=0;i2<64;i2++) s += s_M[tid*64+i2]*__ldg(&qw[tid*64+i2]);
        s_rq[tid] = fmaxf(sqrtf(fmaxf(s,0.f)), 1e-12f);
    }
    __syncthreads();
    for(int i=tid;i<4096;i+=256){
        int r=i>>6, c=i&63; float s=0.f;
        for(int j=0;j<64;j++) s += __ldg(&vw[r*64+j])*s_C[j*64+c];
        s_M[i]=s;
    }
    __syncthreads();
    if(tid<64){
        float s=0.f;
        for(int i2=0;i2<64;i2++) s += s_M[tid*64+i2]*__ldg(&vw[tid*64+i2]);
        s_rv[tid] = fmaxf(sqrtf(fmaxf(s,0.f)), 1e-12f);
    }
    __syncthreads();
    for(int i=tid;i<4096;i+=256) s_M[i]=0.f;
    __syncthreads();
    if(tid<64){
        int h=tid>>3, d=tid&7;
        const float scale = 0.35355339059327373f;
        float l[8], mx=-1e30f;
        for(int e=0;e<8;e++){
            l[e] = s_G[h*64+d*8+e]*scale/(s_rq[h*8+d]*s_rk[h*8+e]);
            mx = fmaxf(mx, l[e]);
        }
        float sum=0.f;
        for(int e=0;e<8;e++){ l[e]=expf(l[e]-mx); sum+=l[e]; }
        float inv=1.f/sum;
        for(int e=0;e<8;e++)
            s_M[(h*8+d)*64 + h*8+e] = l[e]*inv / s_rv[h*8+e];
    }
    __syncthreads();
    for(int i=tid;i<4096;i+=256){
        int r=i>>6, c=i&63, h=c>>3;
        float s=0.f;
        for(int d=0;d<8;d++){ int m=h*8+d; s += __ldg(&pw[r*64+m])*s_M[m*64+c]; }
        s_C[i]=s;
    }
    __syncthreads();
    for(int i=tid;i<4096;i+=256){
        int r=i>>6, c=i&63;
        float s=0.f;
        for(int m=0;m<64;m++) s += s_C[r*64+m]*__ldg(&vw[m*64+c]);
        g_W3[b*4096+i]=s;
    }
}

// ---------------- K6a: y = x + W3*hc (packed) ----------------
__global__ void __launch_bounds__(256,2) k_resid1a(const float* __restrict__ x){
    __shared__ __align__(16) float s_w3[4096];
    int tid = threadIdx.x;
    int i = blockIdx.x*256 + tid;
    int b = i>>16, n = i&(NN-1);
    for(int j=tid;j<4096;j+=256) s_w3[j] = g_W3[b*4096+j];
    const float* hp = g_hc + b*64*NN + n;
    const float* xp = x    + b*64*NN + n;
    ull hc2[32];
#pragma unroll
    for(int j=0;j<32;j++){
        float u = hp[(2*j)*NN], v = hp[(2*j+1)*NN];
        hc2[j] = pk(u,v);
    }
    __syncthreads();
    float* yp = g_y + b*64*NN + n;
#pragma unroll 1
    for(int c=0;c<64;c++){
        const ulonglong2* w2 = (const ulonglong2*)(s_w3 + c*64);
        ull accA=0ULL, accB=0ULL;
#pragma unroll
        for(int j=0;j<16;j++){
            ulonglong2 w = w2[j];
            accA = ffma2(w.x, hc2[2*j  ], accA);
            accB = ffma2(w.y, hc2[2*j+1], accB);
        }
        float a0,a1,b0,b1; upk(accA,a0,a1); upk(accB,b0,b1);
        yp[c*NN] = xp[c*NN] + ((a0+a1)+(b0+b1));
    }
}

// ---------------- K6b: LN2 + mlp_in (packed) ----------------
__global__ void __launch_bounds__(256,2) k_resid1b(const float* __restrict__ lw,
                                                   const float* __restrict__ lb,
                                                   const float* __restrict__ mw){
    __shared__ __align__(16) float s_mw[8192];
    int tid = threadIdx.x;
    int i = blockIdx.x*256 + tid;
    int b = i>>16, n = i&(NN-1);
    const float* yp = g_y + b*64*NN + n;
    ull a2[32];
    float s = 0.f;
#pragma unroll
    for(int j=0;j<32;j++){
        float u = yp[(2*j)*NN], v = yp[(2*j+1)*NN];
        a2[j] = pk(u,v); s += u+v;
    }
    float mu = s*(1.f/64.f), vs = 0.f;
#pragma unroll
    for(int j=0;j<32;j++){
        float u,v; upk(a2[j],u,v);
        u-=mu; v-=mu; vs += u*u + v*v;
    }
    float rstd = rsqrtf(vs*(1.f/64.f) + EPSV);
#pragma unroll
    for(int j=0;j<32;j++){
        float w0=__ldg(&lw[2*j])*rstd, w1=__ldg(&lw[2*j+1])*rstd;
        float t0=__ldg(&lb[2*j])-mu*w0, t1=__ldg(&lb[2*j+1])-mu*w1;
        a2[j] = ffma2(a2[j], pk(w0,w1), pk(t0,t1));
    }
    float* tp = g_t + b*256*NN + n;
    for(int ch=0;ch<2;ch++){
        for(int j=tid;j<8192;j+=256) s_mw[j] = mw[ch*8192+j];
        __syncthreads();
#pragma unroll 1
        for(int o=0;o<128;o++){
            const ulonglong2* w2 = (const ulonglong2*)(s_mw + o*64);
            ull accA=0ULL, accB=0ULL;
#pragma unroll
            for(int j=0;j<16;j++){
                ulonglong2 w = w2[j];
                accA = ffma2(w.x, a2[2*j  ], accA);
                accB = ffma2(w.y, a2[2*j+1], accB);
            }
            float a0,a1,b0,b1; upk(accA,a0,a1); upk(accB,b0,b1);
            tp[(ch*128+o)*NN] = (a0+a1)+(b0+b1);
        }
        __syncthreads();
    }
}

// ---------------- K7: grouped 3x3 + gate + BN + out proj + residual (packed) ----------------
__global__ void __launch_bounds__(256,2) k_mlp2(const float* __restrict__ dww,
                                                const float* __restrict__ bg,
                                                const float* __restrict__ bb,
                                                const float* __restrict__ bm,
                                                const float* __restrict__ bv,
                                                const float* __restrict__ ow,
                                                float* __restrict__ out){
    __shared__ __align__(16) float s_owT[4096];  // [j][o]
    __shared__ ull s_dwA[1152];                  // packed {dw[2g], dw[2g+1]}[wi]
    __shared__ ull s_dwB[1152];                  // packed {dw[64+2g], dw[65+2g]}[wi]
    __shared__ float s_t[8][10][34];
    int b = blockIdx.z;
    int tx0 = blockIdx.x*32, ty0 = blockIdx.y*8;
    int tid = threadIdx.y*32 + threadIdx.x;
    int px = threadIdx.x, py = threadIdx.y;
    for(int i=tid;i<4096;i+=256){ int o=i&63, j=i>>6; s_owT[j*64+o] = ow[o*64+j]; }
    for(int i=tid;i<1152;i+=256){
        int g = i/36, wi = i - g*36;
        s_dwA[i] = pk(dww[(2*g   )*36+wi], dww[(2*g+1 )*36+wi]);
        s_dwB[i] = pk(dww[(64+2*g)*36+wi], dww[(65+2*g)*36+wi]);
    }
    ull acc2[32];
#pragma unroll
    for(int m=0;m<32;m++) acc2[m]=0ULL;
    for(int g=0; g<32; g++){
        __syncthreads();
        for(int i=tid;i<2720;i+=256){
            int ch = i/340, rem = i - ch*340, r = rem/34, cc = rem - r*34;
            int gch = (ch<4) ? (4*g + ch) : (4*(32+g) + ch - 4);
            int gy = ty0 + r - 1;  gy = gy<0 ? -gy : (gy>255 ? 510-gy : gy);
            int gx = tx0 + cc - 1; gx = gx<0 ? -gx : (gx>255 ? 510-gx : gx);
            s_t[ch][r][cc] = g_t[(b*256 + gch)*NN + gy*256 + gx];
        }
        __syncthreads();
        ull a01=0ULL, a23=0ULL;
#pragma unroll
        for(int ci=0;ci<4;ci++)
#pragma unroll
            for(int ky=0;ky<3;ky++)
#pragma unroll
                for(int kx=0;kx<3;kx++){
                    int wi = ci*9 + ky*3 + kx;
                    float t1 = s_t[ci  ][py+ky][px+kx];
                    float t2 = s_t[ci+4][py+ky][px+kx];
                    a01 = ffma2(s_dwA[g*36+wi], pk(t1,t1), a01);
                    a23 = ffma2(s_dwB[g*36+wi], pk(t2,t2), a23);
                }
        float c0,c1,c2,c3;
        upk(a01,c0,c1); upk(a23,c2,c3);
#pragma unroll
        for(int q=0;q<2;q++){
            int j = 2*g + q;
            float v1 = q ? c1 : c0;
            float v2 = q ? c3 : c2;
            float gg = v1/(1.f + __expf(-v1)) * v2;
            gg = (gg - __ldg(&bm[j]))*rsqrtf(__ldg(&bv[j])+EPSV)*__ldg(&bg[j]) + __ldg(&bb[j]);
            ull gg2 = pk(gg,gg);
            const ulonglong2* w2 = (const ulonglong2*)(s_owT + j*64);
#pragma unroll
            for(int m=0;m<16;m++){
                ulonglong2 w = w2[m];
                acc2[2*m  ] = ffma2(w.x, gg2, acc2[2*m  ]);
                acc2[2*m+1] = ffma2(w.y, gg2, acc2[2*m+1]);
            }
        }
    }
    int n = (ty0+py)*256 + tx0+px;
    const float* yp = g_y + b*64*NN + n;
    float* op = out + b*64*NN + n;
#pragma unroll
    for(int m=0;m<32;m++){
        float u,v; upk(acc2[m],u,v);
        op[(2*m  )*NN] = yp[(2*m  )*NN] + u;
        op[(2*m+1)*NN] = yp[(2*m+1)*NN] + v;
    }
}

// ---------------- launcher ----------------
extern "C" void kernel_launch(void* const* d_in, const int* in_sizes, int n_in,
                              void* d_out, int out_size){
    const float* x        = (const float*)d_in[0];
    const float* ln1_w    = (const float*)d_in[1];
    const float* ln1_b    = (const float*)d_in[2];
    const float* ln2_w    = (const float*)d_in[3];
    const float* ln2_b    = (const float*)d_in[4];
    const float* dw_w     = (const float*)d_in[5];
    const float* q_w      = (const float*)d_in[6];
    const float* k_w      = (const float*)d_in[7];
    const float* v_w      = (const float*)d_in[8];
    const float* proj_w   = (const float*)d_in[9];
    const float* mlp_in_w = (const float*)d_in[10];
    const float* mlp_dw_w = (const float*)d_in[11];
    const float* bn_g     = (const float*)d_in[12];
    const float* bn_b     = (const float*)d_in[13];
    const float* bn_m     = (const float*)d_in[14];
    const float* bn_v     = (const float*)d_in[15];
    const float* out_w    = (const float*)d_in[16];
    float* out = (float*)d_out;

    k_ln1    <<<1024, 256>>>(x, ln1_w, ln1_b);
    k_dw1    <<<dim3(8,32,256), dim3(32,8)>>>(dw_w);
    k_cov    <<<dim3(64,4), 256>>>();
    k_covred <<<dim3(16,4), 256>>>();
    k_attn   <<<4, 256>>>(q_w, k_w, v_w, proj_w);
    k_resid1a<<<1024, 256>>>(x);
    k_resid1b<<<1024, 256>>>(ln2_w, ln2_b, mlp_in_w);
    k_mlp2   <<<dim3(8,32,4), dim3(32,8)>>>(mlp_dw_w, bn_g, bn_b, bn_m, bn_v, out_w, out);
}